// round 10
// baseline (speedup 1.0000x reference)
#include <cuda_runtime.h>
#include <cuda_fp16.h>
#include <cstdint>

// ---------------- problem constants ----------------
#define BB   8
#define CCH  256
#define HH   64
#define WW   96
#define ND   21
#define NDD  441
#define HW_  6144            // HH*WW

// ---------------- fp16 swizzled images ----------------
// element (row r, k-unit ku) at  r*512 + ((ku ^ (r&7))*16) + (k&7)*2
#define A_IMG 49152          // 96 rows * 512 B
#define B_IMG 69632          // 136 rows * 512 B (only rows 20..115 written/read)

__device__ __align__(16) unsigned char g_A[(size_t)BB * HH * A_IMG];
__device__ __align__(16) unsigned char g_B[(size_t)BB * HH * B_IMG];

// ---------------- main-kernel smem (relative to 1024-aligned base) ----------
// Prologue: A images (y0 at 0, y1 at 49152). After hoist the same region
// becomes the two 96-data-row B buffers. Zero block for pad-row ldsm reads.
#define SM_B0    0
#define SM_B1    49152
#define SM_ZERO  98304
#define SMEM_REQ (98304 + 4096 + 1024)

// ---------------- ptx helpers (baseline PTX only) -------
__device__ __forceinline__ void cp_async16(uint32_t s, const void* g) {
    asm volatile("cp.async.cg.shared.global [%0], [%1], 16;\n" :: "r"(s), "l"(g));
}
__device__ __forceinline__ void cp_commit() {
    asm volatile("cp.async.commit_group;" ::: "memory");
}
template<int N> __device__ __forceinline__ void cp_wait() {
    asm volatile("cp.async.wait_group %0;" :: "n"(N) : "memory");
}
__device__ __forceinline__ void ldsm4(uint32_t* r, uint32_t a) {
    asm volatile("ldmatrix.sync.aligned.m8n8.x4.shared.b16 {%0,%1,%2,%3}, [%4];"
                 : "=r"(r[0]), "=r"(r[1]), "=r"(r[2]), "=r"(r[3]) : "r"(a));
}
__device__ __forceinline__ void ldsm2(uint32_t* r, uint32_t a) {
    asm volatile("ldmatrix.sync.aligned.m8n8.x2.shared.b16 {%0,%1}, [%2];"
                 : "=r"(r[0]), "=r"(r[1]) : "r"(a));
}
__device__ __forceinline__ void mma16816(float* d, const uint32_t* a, const uint32_t* b) {
    asm volatile("mma.sync.aligned.m16n8k16.row.col.f32.f16.f16.f32 "
                 "{%0,%1,%2,%3}, {%4,%5,%6,%7}, {%8,%9}, {%0,%1,%2,%3};"
                 : "+f"(d[0]), "+f"(d[1]), "+f"(d[2]), "+f"(d[3])
                 : "r"(a[0]), "r"(a[1]), "r"(a[2]), "r"(a[3]), "r"(b[0]), "r"(b[1]));
}

// ================= prepass: one block builds either A or B image for (b,y) ===
__global__ __launch_bounds__(256) void prep_img(const float* __restrict__ in1,
                                                const float* __restrict__ in2) {
    __shared__ float raw[64][97];
    int bid = blockIdx.x;
    bool isB = bid >= (BB * HH);
    int sb = isB ? bid - BB * HH : bid;
    int y = sb & 63, b = sb >> 6;
    int tid = threadIdx.x, w = tid >> 5, lane = tid & 31;
    const float* src_t = isB ? in2 : in1;
    unsigned char* img = isB ? (g_B + (size_t)sb * B_IMG) : (g_A + (size_t)sb * A_IMG);

    for (int q = 0; q < 4; q++) {
        __syncthreads();
        #pragma unroll
        for (int rr = 0; rr < 8; rr++) {
            int c = w * 8 + rr;
            const float* src = src_t + (((size_t)b * CCH + q * 64 + c) * HH + y) * WW;
            #pragma unroll
            for (int m = 0; m < 3; m++)
                raw[c][lane + 32 * m] = src[lane + 32 * m];
        }
        __syncthreads();
        if (!isB) {
            #pragma unroll
            for (int it = 0; it < 3; it++) {
                int u = tid + it * 256;          // u < 768: 96 rows * 8 k-units
                int r = u >> 3, kl = u & 7;
                int ku = q * 8 + kl;
                uint32_t h[4];
                #pragma unroll
                for (int j = 0; j < 4; j++) {
                    __half2 v = __floats2half2_rn(raw[kl * 8 + 2 * j][r],
                                                  raw[kl * 8 + 2 * j + 1][r]);
                    h[j] = *reinterpret_cast<uint32_t*>(&v);
                }
                int off = r * 512 + ((ku ^ (r & 7)) << 4);
                *reinterpret_cast<uint4*>(img + off) = make_uint4(h[0], h[1], h[2], h[3]);
            }
        } else {
            // only data rows 20..115
            #pragma unroll
            for (int it = 0; it < 3; it++) {
                int u = tid + it * 256;          // u < 768
                int r = 20 + (u >> 3), kl = u & 7;
                int ku = q * 8 + kl;
                int xs = r - 20;                 // 0..95 always valid
                uint32_t h[4];
                #pragma unroll
                for (int j = 0; j < 4; j++) {
                    __half2 v = __floats2half2_rn(raw[kl * 8 + 2 * j][xs],
                                                  raw[kl * 8 + 2 * j + 1][xs]);
                    h[j] = *reinterpret_cast<uint32_t*>(&v);
                }
                int off = r * 512 + ((ku ^ (r & 7)) << 4);
                *reinterpret_cast<uint4*>(img + off) = make_uint4(h[0], h[1], h[2], h[3]);
            }
        }
    }
}

// ================= main kernel ================================================
// Block = (b, y-pair (y0, y0+2)). 12 warps = 2 y-rows x 6 m16 tiles; each warp
// does full K=256 (A fragments in registers). One B row serves dy=i for y0 and
// dy=i-1 for y1. Two 96-row B buffers (double-buffered); pad rows -> zero block.
__global__ __launch_bounds__(384, 2) void corr_hmma(float* __restrict__ out) {
    extern __shared__ __align__(16) unsigned char smraw[];
    uint32_t SB = ((uint32_t)__cvta_generic_to_shared(smraw) + 1023u) & ~1023u;

    int bid = blockIdx.x;
    int p = bid & 31, b = bid >> 5;
    int y0 = (p >> 1) * 4 + (p & 1);
    int y1 = y0 + 2;
    int tid = threadIdx.x, w = tid >> 5, lane = tid & 31;
    int yr = w / 6;          // which output row (0 -> y0, 1 -> y1)
    int mt = w % 6;          // m16 tile: x in [16mt, 16mt+16)
    int lg = lane >> 2, t = lane & 3;
    int l7 = lane & 7;
    int yo = yr ? y1 : y0;

    // ---- valid B-row list: i in 0..21, y2 = y0-20+2i ----
    int vlist[22]; int nv = 0;
    #pragma unroll
    for (int i = 0; i < 22; i++) {
        int y2 = y0 - 20 + 2 * i;
        if ((unsigned)y2 < (unsigned)HH) vlist[nv++] = i;
    }

    // ---- prologue: load both A images (y0 -> 0, y1 -> 49152) ----
    {
        const unsigned char* imgA0 = g_A + (size_t)(b * HH + y0) * A_IMG;
        const unsigned char* imgA1 = g_A + (size_t)(b * HH + y1) * A_IMG;
        #pragma unroll
        for (int it = 0; it < 8; it++) {
            int i = tid + it * 384;              // i < 3072
            cp_async16(SB + (uint32_t)(i * 16), imgA0 + (size_t)i * 16);
        }
        #pragma unroll
        for (int it = 0; it < 8; it++) {
            int i = tid + it * 384;
            cp_async16(SB + 49152u + (uint32_t)(i * 16), imgA1 + (size_t)i * 16);
        }
        cp_commit();
    }

    // ---- zero block init (outside A region) ----
    for (int i = tid; i < 256; i += 384) {
        asm volatile("st.shared.v4.b32 [%0], {%1,%1,%1,%1};"
                     :: "r"(SB + SM_ZERO + (uint32_t)(i * 16)), "r"(0) : "memory");
    }

    // ---- zero invalid-dy output slices for both outputs ----
    #pragma unroll 1
    for (int z = 0; z < 2; z++) {
        int yz = z ? y1 : y0;
        #pragma unroll 1
        for (int d = 0; d < ND; d++) {
            int y2 = yz - 20 + 2 * d;
            if ((unsigned)y2 >= (unsigned)HH) {
                for (int i = tid; i < ND * WW; i += 384) {
                    int dj = i / WW, x = i - dj * WW;
                    out[(((size_t)b * NDD + d * ND + dj) * HH + yz) * WW + x] = 0.0f;
                }
            }
        }
    }

    // ---- A resident -> hoist this warp's fragments (full K) ----
    cp_wait<0>();
    __syncthreads();
    uint32_t a[16][4];
    {
        uint32_t arow = 16u * mt + (uint32_t)l7 + 8u * ((lane >> 3) & 1);
        uint32_t abase = SB + (uint32_t)(yr * 49152) + arow * 512u;
        #pragma unroll
        for (int ks = 0; ks < 16; ks++) {
            uint32_t aku = (uint32_t)(2 * ks) + (uint32_t)(lane >> 4);
            ldsm4(a[ks], abase + ((aku ^ (uint32_t)l7) << 4));
        }
    }
    __syncthreads();          // hoists done -> region becomes B0/B1

    // ---- staging: B image data rows 20..115 into buffer idx&1 ----
    auto stage = [&](int idx) {
        int y2 = y0 - 20 + 2 * vlist[idx];
        const unsigned char* src = g_B + (size_t)(b * HH + y2) * B_IMG + 10240;
        uint32_t dst = SB + ((idx & 1) ? SM_B1 : SM_B0);
        #pragma unroll
        for (int it = 0; it < 8; it++) {
            int i = tid + it * 384;              // i < 3072
            cp_async16(dst + (uint32_t)(i * 16), src + (size_t)i * 16);
        }
    };
    stage(0); cp_commit();
    stage(1); cp_commit();

    // ---- B ldsm addresses: 4 per buffer, pad rows -> zero block ----
    uint32_t ad0[4], ad1[4];
    {
        uint32_t zaddr = SB + SM_ZERO + (uint32_t)(l7 * 512);
        #pragma unroll
        for (int q = 0; q < 4; q++) {
            int row = (q < 3) ? (8 * (2 * mt + 2 * q + (lane >> 4)) + l7)
                              : (8 * (2 * mt + 6) + l7);
            bool inb = (row >= 20) && (row < 116);
            uint32_t off = (uint32_t)((row - 20) * 512);
            ad0[q] = inb ? (SB + SM_B0 + off) : zaddr;
            ad1[q] = inb ? (SB + SM_B1 + off) : zaddr;
        }
    }
    uint32_t bkadd = (uint32_t)((lane >> 3) & 1);
    const float scale = 1.0f / 256.0f;

    // ---- pipeline over valid B rows ----
    #pragma unroll 1
    for (int idx = 0; idx < nv; idx++) {
        if (idx + 1 < nv) cp_wait<1>(); else cp_wait<0>();
        __syncthreads();

        int vi = vlist[idx];
        int d_mine = yr ? (vi - 1) : vi;
        bool valid = yr ? (vi >= 1) : (vi <= 20);

        float acc[7][4];
        if (valid) {
            uint32_t c0 = (idx & 1) ? ad1[0] : ad0[0];
            uint32_t c1 = (idx & 1) ? ad1[1] : ad0[1];
            uint32_t c2 = (idx & 1) ? ad1[2] : ad0[2];
            uint32_t c3 = (idx & 1) ? ad1[3] : ad0[3];

            #pragma unroll
            for (int jj = 0; jj < 7; jj++)
                #pragma unroll
                for (int r = 0; r < 4; r++) acc[jj][r] = 0.0f;

            #pragma unroll
            for (int ks = 0; ks < 16; ks++) {
                uint32_t sw = (((uint32_t)(2 * ks) + bkadd) ^ (uint32_t)l7) << 4;
                uint32_t bfr[7][2];
                ldsm4(&bfr[0][0], c0 + sw);
                ldsm4(&bfr[2][0], c1 + sw);
                ldsm4(&bfr[4][0], c2 + sw);
                ldsm2(&bfr[6][0], c3 + sw);
                #pragma unroll
                for (int jj = 0; jj < 7; jj++)
                    mma16816(acc[jj], a[ks], bfr[jj]);
            }
        }

        __syncthreads();                       // all readers done with buffer idx&1
        if (idx + 2 < nv) { stage(idx + 2); cp_commit(); }

        // ---- epilogue from registers (overlaps next stage) ----
        if (valid) {
            size_t obase = (((size_t)b * NDD + d_mine * ND) * HH + yo) * WW;
            #pragma unroll
            for (int jj = 0; jj < 7; jj++) {
                #pragma unroll
                for (int rh = 0; rh < 2; rh++) {
                    int di = 4 * jj - 4 * rh + t - (lg >> 1);
                    float v = (lg & 1) ? acc[jj][2 * rh + 1] : acc[jj][2 * rh];
                    int x = 16 * mt + lg + 8 * rh;
                    if ((unsigned)di <= 20u)
                        out[obase + (size_t)di * HW_ + x] = v * scale;
                }
            }
        }
    }
}

// ================= launch =================
extern "C" void kernel_launch(void* const* d_in, const int* in_sizes, int n_in,
                              void* d_out, int out_size)
{
    const float* in1 = (const float*)d_in[0];
    const float* in2 = (const float*)d_in[1];
    float* out = (float*)d_out;

    cudaFuncSetAttribute(corr_hmma, cudaFuncAttributeMaxDynamicSharedMemorySize, SMEM_REQ);

    prep_img<<<2 * BB * HH, 256>>>(in1, in2);
    corr_hmma<<<BB * (HH / 2), 384, SMEM_REQ>>>(out);
}

// round 11
// speedup vs baseline: 1.4810x; 1.4810x over previous
#include <cuda_runtime.h>
#include <cuda_fp16.h>
#include <cstdint>

// ---------------- problem constants ----------------
#define BB   8
#define CCH  256
#define HH   64
#define WW   96
#define ND   21
#define NDD  441
#define HW_  6144            // HH*WW

// ---------------- fp16 swizzled parity images ----------------
// image row r in [0,96): parity p = r/48, u = r%48, x = 2u+p.
// element (row r, k-unit ku) at  r*512 + ((ku ^ (r&7))*16) + (k&7)*2
#define IMG_SZ 49152         // 96 rows * 512 B

__device__ __align__(16) unsigned char g_A[(size_t)BB * HH * IMG_SZ];
__device__ __align__(16) unsigned char g_B[(size_t)BB * HH * IMG_SZ];

// ---------------- main-kernel smem (relative to 1024-aligned base) ----------
#define SM_A    0
#define SM_B0   49152        // group-0 B buffer
#define SM_B1   98304        // group-1 B buffer
#define SMEM_REQ (147456 + 1024)

// ---------------- ptx helpers (baseline PTX only) -------
__device__ __forceinline__ void cp_async16(uint32_t s, const void* g) {
    asm volatile("cp.async.cg.shared.global [%0], [%1], 16;\n" :: "r"(s), "l"(g));
}
__device__ __forceinline__ void cp_commit() {
    asm volatile("cp.async.commit_group;" ::: "memory");
}
template<int N> __device__ __forceinline__ void cp_wait() {
    asm volatile("cp.async.wait_group %0;" :: "n"(N) : "memory");
}
__device__ __forceinline__ void bar_sync(int id, int cnt) {
    asm volatile("bar.sync %0, %1;" :: "r"(id), "r"(cnt) : "memory");
}
__device__ __forceinline__ void ldsm4(uint32_t* r, uint32_t a) {
    asm volatile("ldmatrix.sync.aligned.m8n8.x4.shared.b16 {%0,%1,%2,%3}, [%4];"
                 : "=r"(r[0]), "=r"(r[1]), "=r"(r[2]), "=r"(r[3]) : "r"(a));
}
__device__ __forceinline__ void mma16816(float* d, const uint32_t* a, const uint32_t* b) {
    asm volatile("mma.sync.aligned.m16n8k16.row.col.f32.f16.f16.f32 "
                 "{%0,%1,%2,%3}, {%4,%5,%6,%7}, {%8,%9}, {%0,%1,%2,%3};"
                 : "+f"(d[0]), "+f"(d[1]), "+f"(d[2]), "+f"(d[3])
                 : "r"(a[0]), "r"(a[1]), "r"(a[2]), "r"(a[3]), "r"(b[0]), "r"(b[1]));
}

// ================= prepass: parity-split fp16 swizzled image of one row =====
// Identical transform for A (in1) and B (in2): row r -> x = 2*(r%48) + r/48.
__global__ __launch_bounds__(256) void prep_img(const float* __restrict__ in1,
                                                const float* __restrict__ in2) {
    __shared__ float raw[64][97];
    int bid = blockIdx.x;
    bool isB = bid >= (BB * HH);
    int sb = isB ? bid - BB * HH : bid;
    int y = sb & 63, b = sb >> 6;
    int tid = threadIdx.x, w = tid >> 5, lane = tid & 31;
    const float* src_t = isB ? in2 : in1;
    unsigned char* img = (isB ? g_B : g_A) + (size_t)sb * IMG_SZ;

    for (int q = 0; q < 4; q++) {
        __syncthreads();
        #pragma unroll
        for (int rr = 0; rr < 8; rr++) {
            int c = w * 8 + rr;
            const float* src = src_t + (((size_t)b * CCH + q * 64 + c) * HH + y) * WW;
            #pragma unroll
            for (int m = 0; m < 3; m++)
                raw[c][lane + 32 * m] = src[lane + 32 * m];
        }
        __syncthreads();
        #pragma unroll
        for (int it = 0; it < 3; it++) {
            int u = tid + it * 256;              // u < 768: 96 rows * 8 k-units
            int r = u >> 3, kl = u & 7;
            int ku = q * 8 + kl;
            int x = (r < 48) ? (2 * r) : (2 * r - 95);   // parity-split mapping
            uint32_t h[4];
            #pragma unroll
            for (int j = 0; j < 4; j++) {
                __half2 v = __floats2half2_rn(raw[kl * 8 + 2 * j][x],
                                              raw[kl * 8 + 2 * j + 1][x]);
                h[j] = *reinterpret_cast<uint32_t*>(&v);
            }
            int off = r * 512 + ((ku ^ (r & 7)) << 4);
            *reinterpret_cast<uint4*>(img + off) = make_uint4(h[0], h[1], h[2], h[3]);
        }
    }
}

// ================= main kernel ================================================
// Block = (b, y). 12 warps = 2 pipeline groups x (2 parities x 3 m16 tiles).
// Each warp: full K=256 (A fragments hoisted to registers), banded n8 tiles
// (mt=0: jj 2..5, mt=1: jj 0..5, mt=2: jj 0..3). Group g handles dy rows
// vi ≡ g (mod 2) out of its own B buffer (named-barrier sync only).
__global__ __launch_bounds__(384, 1) void corr_hmma(float* __restrict__ out) {
    extern __shared__ __align__(16) unsigned char smraw[];
    uint32_t SB = ((uint32_t)__cvta_generic_to_shared(smraw) + 1023u) & ~1023u;

    int bid = blockIdx.x;
    int y = bid & 63, b = bid >> 6;
    int tid = threadIdx.x, w = tid >> 5, lane = tid & 31;
    int g  = w / 6;          // pipeline group
    int wl = w - g * 6;
    int par = wl / 3;        // parity (0: x even, 1: x odd)
    int mt  = wl % 3;        // m16 tile within parity: u in [16mt, 16mt+16)
    int t192 = tid - g * 192;
    int lg = lane >> 2, t = lane & 3;
    int l7 = lane & 7;

    // ---- valid dy list ----
    int vlist[ND]; int nv = 0;
    #pragma unroll
    for (int d = 0; d < ND; d++) {
        int y2 = y - 20 + 2 * d;
        if ((unsigned)y2 < (unsigned)HH) vlist[nv++] = d;
    }

    // ---- staging: full 96-row B image into this group's buffer ----
    auto stage = [&](int vi) {
        int y2 = y - 20 + 2 * vlist[vi];
        const unsigned char* src = g_B + (size_t)(b * HH + y2) * IMG_SZ;
        uint32_t dst = SB + (g ? SM_B1 : SM_B0);
        #pragma unroll
        for (int it = 0; it < 16; it++) {
            int i = t192 + it * 192;             // i < 3072
            cp_async16(dst + (uint32_t)(i * 16), src + (size_t)i * 16);
        }
    };

    // ---- prologue: A image (G0), then this group's first B row (G1) ----
    const unsigned char* imgA = g_A + (size_t)bid * IMG_SZ;
    #pragma unroll
    for (int it = 0; it < 8; it++) {
        int i = tid + it * 384;                  // i < 3072
        cp_async16(SB + SM_A + (uint32_t)(i * 16), imgA + (size_t)i * 16);
    }
    cp_commit();
    if (g < nv) stage(g);
    cp_commit();

    // ---- zero invalid-dy output slices ----
    #pragma unroll 1
    for (int d = 0; d < ND; d++) {
        int y2 = y - 20 + 2 * d;
        if ((unsigned)y2 >= (unsigned)HH) {
            for (int i = tid; i < ND * WW; i += 384) {
                int dj = i / WW, x = i - dj * WW;
                out[(((size_t)b * NDD + d * ND + dj) * HH + y) * WW + x] = 0.0f;
            }
        }
    }

    // ---- A resident -> hoist this warp's fragments (full K=256) ----
    cp_wait<1>();
    __syncthreads();
    uint32_t a[16][4];
    {
        uint32_t arow = (uint32_t)(48 * par + 16 * mt) + (uint32_t)l7 + 8u * ((lane >> 3) & 1);
        uint32_t abase = SB + SM_A + arow * 512u;
        #pragma unroll
        for (int ks = 0; ks < 16; ks++) {
            uint32_t aku = (uint32_t)(2 * ks) + (uint32_t)(lane >> 4);
            ldsm4(a[ks], abase + ((aku ^ (uint32_t)l7) << 4));
        }
    }

    // ---- B ldsm pair addresses: q = 0..2 covers tiles jj = 2q, 2q+1 ----
    // tile jj base v-row: 8*(2mt+jj) - 16; valid pairs: mt=0 -> q 1..2,
    // mt=1 -> q 0..2, mt=2 -> q 0..1 (fully in/out, 8-aligned band).
    int qlo = (mt == 0) ? 1 : 0;
    int qhi = (mt == 2) ? 1 : 2;
    uint32_t bq[3];
    uint32_t bbuf = SB + (g ? SM_B1 : SM_B0);
    #pragma unroll
    for (int q = 0; q < 3; q++) {
        int row = 48 * par + 8 * (2 * mt + 2 * q + (lane >> 4)) - 16 + l7;
        bq[q] = bbuf + (uint32_t)(row * 512);
    }
    uint32_t kadd = (uint32_t)((lane >> 3) & 1);
    const float scale = 1.0f / 256.0f;

    // ---- group pipeline over this group's dy rows ----
    #pragma unroll 1
    for (int vi = g; vi < nv; vi += 2) {
        cp_wait<0>();                        // B(vi) landed (this thread's chain)
        bar_sync(g + 1, 192);                // group-wide visibility

        float acc[6][4];
        #pragma unroll
        for (int jj = 0; jj < 6; jj++)
            #pragma unroll
            for (int r = 0; r < 4; r++) acc[jj][r] = 0.0f;

        #pragma unroll
        for (int ks = 0; ks < 16; ks++) {
            uint32_t sw = (((uint32_t)(2 * ks) + kadd) ^ (uint32_t)l7) << 4;
            #pragma unroll
            for (int q = 0; q < 3; q++) {
                if (q >= qlo && q <= qhi) {
                    uint32_t bfr[2][2];
                    ldsm4(&bfr[0][0], bq[q] + sw);
                    mma16816(acc[2 * q],     a[ks], bfr[0]);
                    mma16816(acc[2 * q + 1], a[ks], bfr[1]);
                }
            }
        }

        bar_sync(g + 1, 192);                // all group warps done reading buffer
        if (vi + 2 < nv) { stage(vi + 2); cp_commit(); }

        // ---- epilogue from registers (all 6 jj; skipped tiles write true 0s) ----
        int dyi = vlist[vi];
        size_t obase = ((size_t)(b * NDD + dyi * ND)) * HW_ + (size_t)y * WW;
        #pragma unroll
        for (int jj = 0; jj < 6; jj++) {
            #pragma unroll
            for (int r = 0; r < 4; r++) {
                int rh = r >> 1;
                int dxj = 8 * jj + 2 * t + (r & 1) - lg - 8 * rh - 6;
                int x = 32 * mt + 2 * lg + 16 * rh + par;
                if ((unsigned)dxj <= 20u)
                    out[obase + (size_t)dxj * HW_ + x] = acc[jj][r] * scale;
            }
        }
    }
}

// ================= launch =================
extern "C" void kernel_launch(void* const* d_in, const int* in_sizes, int n_in,
                              void* d_out, int out_size)
{
    const float* in1 = (const float*)d_in[0];
    const float* in2 = (const float*)d_in[1];
    float* out = (float*)d_out;

    cudaFuncSetAttribute(corr_hmma, cudaFuncAttributeMaxDynamicSharedMemorySize, SMEM_REQ);

    prep_img<<<2 * BB * HH, 256>>>(in1, in2);
    corr_hmma<<<BB * HH, 384, SMEM_REQ>>>(out);
}